// round 9
// baseline (speedup 1.0000x reference)
#include <cuda_runtime.h>
#include <math_constants.h>
#include <stdint.h>

#define NMAX 131072
#define C_DIM 1000
#define NBINS 10
#define HIST_BLOCKS 148
#define HIST_THREADS 256

// ---- scratch (no allocations allowed) ----
// Statically initialized to the state every call expects at entry; the LAST
// hist block restores this exact state after computing the output, so every
// graph replay sees identical initial conditions (no init launch needed).
__device__ float g_values[NMAX];
__device__ int   g_vmax_bits = 0xFF800000;              // -inf bits
__device__ int   g_counts[NBINS] = {0};
__device__ float g_sums[NBINS]   = {0.0f};
__device__ unsigned int g_ticket = 0;

// ---------------------------------------------------------------------------
// One warp per row: single HBM pass over the row kept in registers.
// values[r] = log(sum exp(x - m)) + m - x[target]; block-reduced atomicMax.
// (R7 version — measured fastest CE.)
__global__ __launch_bounds__(256) void ghm_ce_kernel(
    const float* __restrict__ pred,
    const int*   __restrict__ target,   // int32 (JAX w/o x64 demotes int64 -> int32)
    int N)
{
    // PDL: allow the dependent (hist) grid to launch/ramp as we drain.
    asm volatile("griddepcontrol.launch_dependents;" ::: "memory");

    const int warp_in_blk = threadIdx.x >> 5;
    const int lane        = threadIdx.x & 31;
    const int row         = blockIdx.x * (blockDim.x >> 5) + warp_in_blk;

    __shared__ float s_wmax[8];

    float val = -CUDART_INF_F;
    if (row < N) {
        const float4* row4 = reinterpret_cast<const float4*>(pred + (size_t)row * C_DIM);

        // Hoisted gather: issue early so its latency overlaps the reductions.
        float pt = 0.0f;
        if (lane == 0) {
            int t = target[row];
            t = min(max(t, 0), C_DIM - 1);
            pt = __ldg(pred + (size_t)row * C_DIM + t);
        }

        float4 v[8];
        float m = -CUDART_INF_F;
        #pragma unroll
        for (int j = 0; j < 8; j++) {
            int idx = lane + j * 32;            // 250 float4 per row
            if (idx < 250) {
                v[j] = __ldcs(row4 + idx);      // streaming: read-once data
                m = fmaxf(m, fmaxf(fmaxf(v[j].x, v[j].y), fmaxf(v[j].z, v[j].w)));
            } else {
                v[j] = make_float4(-CUDART_INF_F, -CUDART_INF_F, -CUDART_INF_F, -CUDART_INF_F);
            }
        }
        // warp max
        #pragma unroll
        for (int o = 16; o > 0; o >>= 1)
            m = fmaxf(m, __shfl_xor_sync(0xFFFFFFFFu, m, o));

        // sum exp(x - m) from registers (exp(-inf) == 0 for padding lanes)
        float s = 0.0f;
        #pragma unroll
        for (int j = 0; j < 8; j++) {
            s += __expf(v[j].x - m);
            s += __expf(v[j].y - m);
            s += __expf(v[j].z - m);
            s += __expf(v[j].w - m);
        }
        #pragma unroll
        for (int o = 16; o > 0; o >>= 1)
            s += __shfl_xor_sync(0xFFFFFFFFu, s, o);

        if (lane == 0) {
            val = __logf(s) + m - pt;
            g_values[row] = val;
        }
    }

    // block-level max -> one global atomic per block
    if (lane == 0) s_wmax[warp_in_blk] = val;
    __syncthreads();
    if (threadIdx.x == 0) {
        float bm = s_wmax[0];
        int nw = blockDim.x >> 5;
        for (int w = 1; w < nw; w++) bm = fmaxf(bm, s_wmax[w]);
        if (bm > -CUDART_INF_F)
            atomicMax(&g_vmax_bits, __float_as_int(bm));
    }
}

// ---------------------------------------------------------------------------
// Single-wave histogram: 148 blocks (1/SM), each thread front-batches 4
// strided loads (MLP=4 hides DRAM latency), bins once per element into
// shared, then ticket-final. Replicates searchsorted-right on fp32 edges
// k/10 (last += 1e-6).
__device__ __forceinline__ int ghm_bin(float vc) {
    int j = 0;
    #pragma unroll
    for (int k = 0; k <= NBINS; k++) {
        float e = (float)k / 10.0f;
        if (k == NBINS) e += 1e-6f;
        j += (vc >= e) ? 1 : 0;
    }
    return min(max(j - 1, 0), NBINS - 1);
}

__global__ __launch_bounds__(HIST_THREADS) void ghm_hist_final_kernel(
    int N, float* __restrict__ out)
{
    __shared__ int   sc[NBINS];
    __shared__ float ss[NBINS];
    __shared__ bool  s_last;
    if (threadIdx.x < NBINS) { sc[threadIdx.x] = 0; ss[threadIdx.x] = 0.0f; }
    __syncthreads();

    // PDL: wait for the CE grid's memory (g_values, g_vmax_bits) to be visible.
    asm volatile("griddepcontrol.wait;" ::: "memory");

    const float vmax = __int_as_float(g_vmax_bits);
    const int stride = HIST_BLOCKS * HIST_THREADS;          // 37888
    const int base   = blockIdx.x * HIST_THREADS + threadIdx.x;

    // front-batched independent loads (covers N <= 4*stride = 151552)
    float v0 = 0.f, v1 = 0.f, v2 = 0.f, v3 = 0.f;
    const int i0 = base, i1 = base + stride, i2 = base + 2 * stride, i3 = base + 3 * stride;
    bool b0 = i0 < N, b1 = i1 < N, b2 = i2 < N, b3 = i3 < N;
    if (b0) v0 = g_values[i0];
    if (b1) v1 = g_values[i1];
    if (b2) v2 = g_values[i2];
    if (b3) v3 = g_values[i3];

    if (b0) { int b = ghm_bin(v0 / vmax); atomicAdd(&sc[b], 1); atomicAdd(&ss[b], v0); }
    if (b1) { int b = ghm_bin(v1 / vmax); atomicAdd(&sc[b], 1); atomicAdd(&ss[b], v1); }
    if (b2) { int b = ghm_bin(v2 / vmax); atomicAdd(&sc[b], 1); atomicAdd(&ss[b], v2); }
    if (b3) { int b = ghm_bin(v3 / vmax); atomicAdd(&sc[b], 1); atomicAdd(&ss[b], v3); }

    __syncthreads();
    if (threadIdx.x < NBINS) {
        atomicAdd(&g_counts[threadIdx.x], sc[threadIdx.x]);
        atomicAdd(&g_sums[threadIdx.x],   ss[threadIdx.x]);
    }

    // ---- ticket: last block computes the final scalar ----
    __threadfence();
    if (threadIdx.x == 0) {
        unsigned int prev = atomicAdd(&g_ticket, 1u);
        s_last = (prev == (unsigned int)(HIST_BLOCKS - 1));
    }
    __syncthreads();

    if (s_last && threadIdx.x < 32) {
        int lane = threadIdx.x;
        float contrib = 0.0f;
        float nne = 0.0f;
        if (lane < NBINS) {
            int   c = g_counts[lane];
            float s = g_sums[lane];
            if (c > 0) { contrib = s / (float)c; nne = 1.0f; }
        }
        #pragma unroll
        for (int o = 16; o > 0; o >>= 1) {
            contrib += __shfl_xor_sync(0xFFFFFFFFu, contrib, o);
            nne     += __shfl_xor_sync(0xFFFFFFFFu, nne, o);
        }
        if (lane == 0)
            out[0] = contrib / fmaxf(nne, 1.0f);

        // restore initial state for the next graph replay (stream-ordered
        // strictly before the next call's ghm_ce_kernel)
        if (lane < NBINS) { g_counts[lane] = 0; g_sums[lane] = 0.0f; }
        if (lane == 0)    { g_vmax_bits = 0xFF800000; g_ticket = 0; }
    }
}

// ---------------------------------------------------------------------------
extern "C" void kernel_launch(void* const* d_in, const int* in_sizes, int n_in,
                              void* d_out, int out_size)
{
    const float* pred   = (const float*)d_in[0];
    const int*   target = (const int*)d_in[1];
    float*       out    = (float*)d_out;

    const int N = in_sizes[1];              // 131072 rows; C fixed at 1000

    const int warps_per_blk = 8;            // 256 threads
    int grid1 = (N + warps_per_blk - 1) / warps_per_blk;
    ghm_ce_kernel<<<grid1, 256>>>(pred, target, N);

    // hist+final: single wave, PDL
    cudaLaunchConfig_t cfg = {};
    cfg.gridDim  = dim3(HIST_BLOCKS);
    cfg.blockDim = dim3(HIST_THREADS);
    cfg.dynamicSmemBytes = 0;
    cfg.stream = 0;
    cudaLaunchAttribute attr[1];
    attr[0].id = cudaLaunchAttributeProgrammaticStreamSerialization;
    attr[0].val.programmaticStreamSerializationAllowed = 1;
    cfg.attrs = attr;
    cfg.numAttrs = 1;
    cudaLaunchKernelEx(&cfg, ghm_hist_final_kernel, N, out);
}

// round 10
// speedup vs baseline: 1.1770x; 1.1770x over previous
#include <cuda_runtime.h>
#include <math_constants.h>
#include <stdint.h>

#define NMAX 131072
#define C_DIM 1000
#define NBINS 10

// ---- scratch (no allocations allowed) ----
// Statically initialized to the state every call expects at entry; the LAST
// hist block restores this exact state after computing the output, so every
// graph replay sees identical initial conditions (no init launch needed).
__device__ float g_values[NMAX];
__device__ int   g_vmax_bits = 0xFF800000;              // -inf bits
__device__ int   g_counts[NBINS] = {0};
__device__ float g_sums[NBINS]   = {0.0f};
__device__ unsigned int g_ticket = 0;

// ---------------------------------------------------------------------------
// One warp per row: single HBM pass over the row kept in registers.
// values[r] = log(sum exp(x - m)) + m - x[target]; block-reduced atomicMax.
// (R7 version — measured fastest CE.)
__global__ __launch_bounds__(256) void ghm_ce_kernel(
    const float* __restrict__ pred,
    const int*   __restrict__ target,   // int32 (JAX w/o x64 demotes int64 -> int32)
    int N)
{
    // PDL: allow the dependent (hist) grid to launch/ramp as we drain.
    asm volatile("griddepcontrol.launch_dependents;" ::: "memory");

    const int warp_in_blk = threadIdx.x >> 5;
    const int lane        = threadIdx.x & 31;
    const int row         = blockIdx.x * (blockDim.x >> 5) + warp_in_blk;

    __shared__ float s_wmax[8];

    float val = -CUDART_INF_F;
    if (row < N) {
        const float4* row4 = reinterpret_cast<const float4*>(pred + (size_t)row * C_DIM);

        // Hoisted gather: issue early so its latency overlaps the reductions.
        float pt = 0.0f;
        if (lane == 0) {
            int t = target[row];
            t = min(max(t, 0), C_DIM - 1);
            pt = __ldg(pred + (size_t)row * C_DIM + t);
        }

        float4 v[8];
        float m = -CUDART_INF_F;
        #pragma unroll
        for (int j = 0; j < 8; j++) {
            int idx = lane + j * 32;            // 250 float4 per row
            if (idx < 250) {
                v[j] = __ldcs(row4 + idx);      // streaming: read-once data
                m = fmaxf(m, fmaxf(fmaxf(v[j].x, v[j].y), fmaxf(v[j].z, v[j].w)));
            } else {
                v[j] = make_float4(-CUDART_INF_F, -CUDART_INF_F, -CUDART_INF_F, -CUDART_INF_F);
            }
        }
        // warp max
        #pragma unroll
        for (int o = 16; o > 0; o >>= 1)
            m = fmaxf(m, __shfl_xor_sync(0xFFFFFFFFu, m, o));

        // sum exp(x - m) from registers (exp(-inf) == 0 for padding lanes)
        float s = 0.0f;
        #pragma unroll
        for (int j = 0; j < 8; j++) {
            s += __expf(v[j].x - m);
            s += __expf(v[j].y - m);
            s += __expf(v[j].z - m);
            s += __expf(v[j].w - m);
        }
        #pragma unroll
        for (int o = 16; o > 0; o >>= 1)
            s += __shfl_xor_sync(0xFFFFFFFFu, s, o);

        if (lane == 0) {
            val = __logf(s) + m - pt;
            g_values[row] = val;
        }
    }

    // block-level max -> one global atomic per block
    if (lane == 0) s_wmax[warp_in_blk] = val;
    __syncthreads();
    if (threadIdx.x == 0) {
        float bm = s_wmax[0];
        int nw = blockDim.x >> 5;
        for (int w = 1; w < nw; w++) bm = fmaxf(bm, s_wmax[w]);
        if (bm > -CUDART_INF_F)
            atomicMax(&g_vmax_bits, __float_as_int(bm));
    }
}

// ---------------------------------------------------------------------------
// Histogram with WARP-AGGREGATED bin updates: per warp, ballot+popc gives the
// count per bin and a shuffle reduce gives the value sum, so each warp issues
// at most one shared atomic pair per nonempty bin (values cluster in 1-2 bins
// -> same-address ATOMS serialization was the measured bottleneck).
// Replicates searchsorted-right on fp32 edges k/10 (last += 1e-6).
__device__ __forceinline__ int ghm_bin(float vc) {
    int j = 0;
    #pragma unroll
    for (int k = 0; k <= NBINS; k++) {
        float e = (float)k / 10.0f;
        if (k == NBINS) e += 1e-6f;
        j += (vc >= e) ? 1 : 0;
    }
    return min(max(j - 1, 0), NBINS - 1);
}

__global__ __launch_bounds__(256) void ghm_hist_final_kernel(
    int N, int nblocks, float* __restrict__ out)
{
    __shared__ int   sc[NBINS];
    __shared__ float ss[NBINS];
    __shared__ bool  s_last;
    if (threadIdx.x < NBINS) { sc[threadIdx.x] = 0; ss[threadIdx.x] = 0.0f; }
    __syncthreads();

    // PDL: wait for the CE grid's memory (g_values, g_vmax_bits) to be visible.
    asm volatile("griddepcontrol.wait;" ::: "memory");

    const float vmax = __int_as_float(g_vmax_bits);
    const int lane = threadIdx.x & 31;

    const int i = blockIdx.x * blockDim.x + threadIdx.x;   // 512*256 == N exactly
    const bool valid = i < N;
    float v = 0.0f;
    int   b = -1;
    if (valid) {
        v = g_values[i];
        b = ghm_bin(v / vmax);
    }

    #pragma unroll
    for (int k = 0; k < NBINS; k++) {
        unsigned mask = __ballot_sync(0xFFFFFFFFu, b == k);
        if (mask) {
            float sv = (b == k) ? v : 0.0f;
            #pragma unroll
            for (int o = 16; o > 0; o >>= 1)
                sv += __shfl_xor_sync(0xFFFFFFFFu, sv, o);
            if (lane == 0) {
                atomicAdd(&sc[k], __popc(mask));
                atomicAdd(&ss[k], sv);
            }
        }
    }

    __syncthreads();
    if (threadIdx.x < NBINS) {
        atomicAdd(&g_counts[threadIdx.x], sc[threadIdx.x]);
        atomicAdd(&g_sums[threadIdx.x],   ss[threadIdx.x]);
    }

    // ---- ticket: last block computes the final scalar ----
    __threadfence();
    if (threadIdx.x == 0) {
        unsigned int prev = atomicAdd(&g_ticket, 1u);
        s_last = (prev == (unsigned int)(nblocks - 1));
    }
    __syncthreads();

    if (s_last && threadIdx.x < 32) {
        float contrib = 0.0f;
        float nne = 0.0f;
        if (lane < NBINS) {
            int   c = g_counts[lane];
            float s = g_sums[lane];
            if (c > 0) { contrib = s / (float)c; nne = 1.0f; }
        }
        #pragma unroll
        for (int o = 16; o > 0; o >>= 1) {
            contrib += __shfl_xor_sync(0xFFFFFFFFu, contrib, o);
            nne     += __shfl_xor_sync(0xFFFFFFFFu, nne, o);
        }
        if (lane == 0)
            out[0] = contrib / fmaxf(nne, 1.0f);

        // restore initial state for the next graph replay (stream-ordered
        // strictly before the next call's ghm_ce_kernel)
        if (lane < NBINS) { g_counts[lane] = 0; g_sums[lane] = 0.0f; }
        if (lane == 0)    { g_vmax_bits = 0xFF800000; g_ticket = 0; }
    }
}

// ---------------------------------------------------------------------------
extern "C" void kernel_launch(void* const* d_in, const int* in_sizes, int n_in,
                              void* d_out, int out_size)
{
    const float* pred   = (const float*)d_in[0];
    const int*   target = (const int*)d_in[1];
    float*       out    = (float*)d_out;

    const int N = in_sizes[1];              // 131072 rows; C fixed at 1000

    const int warps_per_blk = 8;            // 256 threads
    int grid1 = (N + warps_per_blk - 1) / warps_per_blk;
    ghm_ce_kernel<<<grid1, 256>>>(pred, target, N);

    // hist+final with programmatic dependent launch; one element per thread
    int grid2 = (N + 255) / 256;            // 512 for N=131072

    cudaLaunchConfig_t cfg = {};
    cfg.gridDim  = dim3((unsigned)grid2);
    cfg.blockDim = dim3(256);
    cfg.dynamicSmemBytes = 0;
    cfg.stream = 0;
    cudaLaunchAttribute attr[1];
    attr[0].id = cudaLaunchAttributeProgrammaticStreamSerialization;
    attr[0].val.programmaticStreamSerializationAllowed = 1;
    cfg.attrs = attr;
    cfg.numAttrs = 1;
    cudaLaunchKernelEx(&cfg, ghm_hist_final_kernel, N, grid2, out);
}

// round 12
// speedup vs baseline: 1.1869x; 1.0084x over previous
#include <cuda_runtime.h>
#include <math_constants.h>
#include <stdint.h>

#define NMAX 131072
#define C_DIM 1000
#define NBINS 10

// ---- scratch (no allocations allowed) ----
// Statically initialized to the state every call expects at entry; the LAST
// hist block restores this exact state after computing the output, so every
// graph replay sees identical initial conditions (no init launch needed).
__device__ float g_values[NMAX];
__device__ int   g_vmax_bits = 0xFF800000;              // -inf bits
__device__ int   g_counts[NBINS] = {0};
__device__ float g_sums[NBINS]   = {0.0f};
__device__ unsigned int g_ticket = 0;

// L2 residency control via cache-hint policy registers (the scalar-compatible
// form; bare .L2::evict_* qualifiers require .v8.b32 on sm_103 ptxas).
__device__ __forceinline__ void st_evict_last(float* p, float v) {
    asm volatile(
        "{\n\t"
        ".reg .b64 pol;\n\t"
        "createpolicy.fractional.L2::evict_last.b64 pol, 1.0;\n\t"
        "st.global.L2::cache_hint.f32 [%0], %1, pol;\n\t"
        "}" :: "l"(p), "f"(v) : "memory");
}
__device__ __forceinline__ float ld_evict_first(const float* p) {
    float v;
    asm volatile(
        "{\n\t"
        ".reg .b64 pol;\n\t"
        "createpolicy.fractional.L2::evict_first.b64 pol, 1.0;\n\t"
        "ld.global.L2::cache_hint.f32 %0, [%1], pol;\n\t"
        "}" : "=f"(v) : "l"(p));
    return v;
}

// ---------------------------------------------------------------------------
// One warp per row: single HBM pass over the row kept in registers.
// values[r] = log(sum exp(x - m)) + m - x[target]; block-reduced atomicMax.
__global__ __launch_bounds__(256) void ghm_ce_kernel(
    const float* __restrict__ pred,
    const int*   __restrict__ target,   // int32 (JAX w/o x64 demotes int64 -> int32)
    int N)
{
    // PDL: allow the dependent (hist) grid to launch/ramp as we drain.
    asm volatile("griddepcontrol.launch_dependents;" ::: "memory");

    const int warp_in_blk = threadIdx.x >> 5;
    const int lane        = threadIdx.x & 31;
    const int row         = blockIdx.x * (blockDim.x >> 5) + warp_in_blk;

    __shared__ float s_wmax[8];

    float val = -CUDART_INF_F;
    if (row < N) {
        const float4* row4 = reinterpret_cast<const float4*>(pred + (size_t)row * C_DIM);

        // Hoisted gather: issue early so its latency overlaps the reductions.
        float pt = 0.0f;
        if (lane == 0) {
            int t = target[row];
            t = min(max(t, 0), C_DIM - 1);
            pt = __ldg(pred + (size_t)row * C_DIM + t);
        }

        float4 v[8];
        float m = -CUDART_INF_F;
        #pragma unroll
        for (int j = 0; j < 8; j++) {
            int idx = lane + j * 32;            // 250 float4 per row
            if (idx < 250) {
                v[j] = __ldcs(row4 + idx);      // streaming: read-once data, evict-first
                m = fmaxf(m, fmaxf(fmaxf(v[j].x, v[j].y), fmaxf(v[j].z, v[j].w)));
            } else {
                v[j] = make_float4(-CUDART_INF_F, -CUDART_INF_F, -CUDART_INF_F, -CUDART_INF_F);
            }
        }
        // warp max
        #pragma unroll
        for (int o = 16; o > 0; o >>= 1)
            m = fmaxf(m, __shfl_xor_sync(0xFFFFFFFFu, m, o));

        // sum exp(x - m) from registers (exp(-inf) == 0 for padding lanes)
        float s = 0.0f;
        #pragma unroll
        for (int j = 0; j < 8; j++) {
            s += __expf(v[j].x - m);
            s += __expf(v[j].y - m);
            s += __expf(v[j].z - m);
            s += __expf(v[j].w - m);
        }
        #pragma unroll
        for (int o = 16; o > 0; o >>= 1)
            s += __shfl_xor_sync(0xFFFFFFFFu, s, o);

        if (lane == 0) {
            val = __logf(s) + m - pt;
            st_evict_last(&g_values[row], val);   // keep L2-resident for hist
        }
    }

    // block-level max -> one global atomic per block
    if (lane == 0) s_wmax[warp_in_blk] = val;
    __syncthreads();
    if (threadIdx.x == 0) {
        float bm = s_wmax[0];
        int nw = blockDim.x >> 5;
        for (int w = 1; w < nw; w++) bm = fmaxf(bm, s_wmax[w]);
        if (bm > -CUDART_INF_F)
            atomicMax(&g_vmax_bits, __float_as_int(bm));
    }
}

// ---------------------------------------------------------------------------
// Histogram with WARP-AGGREGATED bin updates: per warp, ballot+popc gives the
// count per bin and a shuffle reduce gives the value sum, so each warp issues
// at most one shared atomic pair per nonempty bin. Replicates
// searchsorted-right on fp32 edges k/10 (last += 1e-6).
__device__ __forceinline__ int ghm_bin(float vc) {
    int j = 0;
    #pragma unroll
    for (int k = 0; k <= NBINS; k++) {
        float e = (float)k / 10.0f;
        if (k == NBINS) e += 1e-6f;
        j += (vc >= e) ? 1 : 0;
    }
    return min(max(j - 1, 0), NBINS - 1);
}

__global__ __launch_bounds__(256) void ghm_hist_final_kernel(
    int N, int nblocks, float* __restrict__ out)
{
    __shared__ int   sc[NBINS];
    __shared__ float ss[NBINS];
    __shared__ bool  s_last;
    if (threadIdx.x < NBINS) { sc[threadIdx.x] = 0; ss[threadIdx.x] = 0.0f; }
    __syncthreads();

    // PDL: wait for the CE grid's memory (g_values, g_vmax_bits) to be visible.
    asm volatile("griddepcontrol.wait;" ::: "memory");

    const float vmax = __int_as_float(g_vmax_bits);
    const int lane = threadIdx.x & 31;

    const int i = blockIdx.x * blockDim.x + threadIdx.x;   // 512*256 == N exactly
    const bool valid = i < N;
    float v = 0.0f;
    int   b = -1;
    if (valid) {
        v = ld_evict_first(&g_values[i]);   // read-once, should be L2-hit
        b = ghm_bin(v / vmax);
    }

    #pragma unroll
    for (int k = 0; k < NBINS; k++) {
        unsigned mask = __ballot_sync(0xFFFFFFFFu, b == k);
        if (mask) {
            float sv = (b == k) ? v : 0.0f;
            #pragma unroll
            for (int o = 16; o > 0; o >>= 1)
                sv += __shfl_xor_sync(0xFFFFFFFFu, sv, o);
            if (lane == 0) {
                atomicAdd(&sc[k], __popc(mask));
                atomicAdd(&ss[k], sv);
            }
        }
    }

    __syncthreads();
    if (threadIdx.x < NBINS) {
        atomicAdd(&g_counts[threadIdx.x], sc[threadIdx.x]);
        atomicAdd(&g_sums[threadIdx.x],   ss[threadIdx.x]);
    }

    // ---- ticket: last block computes the final scalar ----
    __threadfence();
    if (threadIdx.x == 0) {
        unsigned int prev = atomicAdd(&g_ticket, 1u);
        s_last = (prev == (unsigned int)(nblocks - 1));
    }
    __syncthreads();

    if (s_last && threadIdx.x < 32) {
        float contrib = 0.0f;
        float nne = 0.0f;
        if (lane < NBINS) {
            int   c = g_counts[lane];
            float s = g_sums[lane];
            if (c > 0) { contrib = s / (float)c; nne = 1.0f; }
        }
        #pragma unroll
        for (int o = 16; o > 0; o >>= 1) {
            contrib += __shfl_xor_sync(0xFFFFFFFFu, contrib, o);
            nne     += __shfl_xor_sync(0xFFFFFFFFu, nne, o);
        }
        if (lane == 0)
            out[0] = contrib / fmaxf(nne, 1.0f);

        // restore initial state for the next graph replay (stream-ordered
        // strictly before the next call's ghm_ce_kernel)
        if (lane < NBINS) { g_counts[lane] = 0; g_sums[lane] = 0.0f; }
        if (lane == 0)    { g_vmax_bits = 0xFF800000; g_ticket = 0; }
    }
}

// ---------------------------------------------------------------------------
extern "C" void kernel_launch(void* const* d_in, const int* in_sizes, int n_in,
                              void* d_out, int out_size)
{
    const float* pred   = (const float*)d_in[0];
    const int*   target = (const int*)d_in[1];
    float*       out    = (float*)d_out;

    const int N = in_sizes[1];              // 131072 rows; C fixed at 1000

    const int warps_per_blk = 8;            // 256 threads
    int grid1 = (N + warps_per_blk - 1) / warps_per_blk;
    ghm_ce_kernel<<<grid1, 256>>>(pred, target, N);

    // hist+final with programmatic dependent launch; one element per thread
    int grid2 = (N + 255) / 256;            // 512 for N=131072

    cudaLaunchConfig_t cfg = {};
    cfg.gridDim  = dim3((unsigned)grid2);
    cfg.blockDim = dim3(256);
    cfg.dynamicSmemBytes = 0;
    cfg.stream = 0;
    cudaLaunchAttribute attr[1];
    attr[0].id = cudaLaunchAttributeProgrammaticStreamSerialization;
    attr[0].val.programmaticStreamSerializationAllowed = 1;
    cfg.attrs = attr;
    cfg.numAttrs = 1;
    cudaLaunchKernelEx(&cfg, ghm_hist_final_kernel, N, grid2, out);
}